// round 7
// baseline (speedup 1.0000x reference)
#include <cuda_runtime.h>

#define NB   2048
#define SRC  64
#define PAD  32

#define FMAGIC 8388608.0f   // 2^23
// bits(2^23 + v) = 0x4B000000 + v for v in [0, 2^23). Fold both axes + (-32,-32):
// idx = by*64 + bx + KFOLD  ==  (y0c-32)*64 + (x0c-32)
#define KFOLD (0u - (0x4B000000u * 65u + 2080u))

__global__ void __launch_bounds__(512, 3)
affine_sampler_kernel(const float* __restrict__ affine,   // (N,6)
                      const float* __restrict__ fill,     // (N,64,64)
                      const float* __restrict__ stroke,   // (N,64,64)
                      float* __restrict__ out_fill,       // (N,128,128)
                      float* __restrict__ out_stroke)     // (N,128,128)
{
    // tile + 65-entry zero pads front/back: indices used run [-65, 4160]
    __shared__ float2 t2raw[4226];
    float2* const T2 = t2raw + 65;

    const int n   = blockIdx.x;
    const int tid = threadIdx.x;

    // ---- zero the pads ----
    if (tid < 65) {
        t2raw[tid]        = make_float2(0.f, 0.f);
        t2raw[4161 + tid] = make_float2(0.f, 0.f);
    }

    // ---- stage + interleave source tiles (float4 global reads, coalesced) ----
    {
        const float4* gf = (const float4*)(fill   + (size_t)n * SRC * SRC);
        const float4* gs = (const float4*)(stroke + (size_t)n * SRC * SRC);
        #pragma unroll
        for (int i = 0; i < 2; i++) {
            const int v = tid + i * 512;          // float4 index 0..1023
            float4 f  = gf[v];
            float4 st = gs[v];
            float2* dst = &T2[v * 4];
            dst[0] = make_float2(f.x, st.x);
            dst[1] = make_float2(f.y, st.y);
            dst[2] = make_float2(f.z, st.z);
            dst[3] = make_float2(f.w, st.w);
        }
    }

    // ---- theta (broadcast loads; every thread computes) ----
    const float* a = affine + n * 6;
    const float a00 = 2.0f / (1.0f + __expf(-a[0]));
    const float a11 = 2.0f / (1.0f + __expf(-a[1]));
    const float a01 = 2.0f * tanhf(a[2]);
    const float a10 = 2.0f * tanhf(a[3]);
    const float a02 = tanhf(a[4]);
    const float a12 = tanhf(a[5]);

    // Folded chain: ix = a00*x + a01*y + Cx  (pixel coords in padded 128x128 img)
    const float Cx = 64.0f * a02 + 63.5f - 63.5f * (a00 + a01);
    const float Cy = 64.0f * a12 + 63.5f - 63.5f * (a10 + a11);

    // row-endpoint deltas over x in [0,127]; a00 > 0 always, a10 sign unknown
    const float ex = 127.0f * a00;
    const float ey = 127.0f * a10;

    __syncthreads();

    float* of = out_fill   + (size_t)n * 128 * 128;
    float* os = out_stroke + (size_t)n * 128 * 128;

    const int lane = tid & 31;
    const int warp = tid >> 5;              // 0..15; warp owns whole rows
    const float xf = (float)(lane << 2);    // 4 contiguous pixels per lane

    #pragma unroll 1
    for (int it = 0; it < 8; it++) {
        const int   row = it * 16 + warp;
        const float yf  = (float)row;

        // row-start coords (x=0) and row extremes over x in [0,127]
        const float rx0 = fmaf(a01, yf, Cx);
        const float ry0 = fmaf(a11, yf, Cy);
        const float lox = rx0;               // a00 > 0
        const float hix = rx0 + ex;
        const float loy = fminf(ry0, ry0 + ey);
        const float hiy = fmaxf(ry0, ry0 + ey);

        // warp-uniform: entire row exactly zero? (pixel nonzero needs ix,iy in [31,96))
        // margins absorb fp drift; marginal rows take the exact work path
        const bool zero = (hix <= 30.99f) | (lox >= 96.01f) |
                          (hiy <= 30.99f) | (loy >= 96.01f);

        const int o = row * 128 + (lane << 2);

        if (zero) {
            const float4 z = make_float4(0.f, 0.f, 0.f, 0.f);
            __stcs((float4*)&of[o], z);
            __stcs((float4*)&os[o], z);
            continue;
        }

        // ---- branchless work path: sel-zeroed weights, always-valid LDS ----
        float ix = fmaf(a00, xf, rx0);
        float iy = fmaf(a10, xf, ry0);

        float4 rf, rs;
        float* rfp = &rf.x;
        float* rsp = &rs.x;

        #pragma unroll
        for (int k = 0; k < 4; k++) {
            // raw magic floor -> weights (garbage-but-finite when out of range;
            // those weights are sel'ed to zero below)
            const float txr = __fadd_rz(ix, FMAGIC);
            const float tyr = __fadd_rz(iy, FMAGIC);
            const float x0f = txr - FMAGIC;
            const float y0f = tyr - FMAGIC;
            const float wx = ix - x0f;
            const float wy = iy - y0f;
            const float mx = 1.0f - wx;
            const float my = 1.0f - wy;

            // clamped magic floor -> always-in-pad index
            const float cxf = fminf(fmaxf(ix, 31.0f), 95.0f);
            const float cyf = fminf(fmaxf(iy, 31.0f), 95.0f);
            const unsigned bx = (unsigned)__float_as_int(__fadd_rz(cxf, FMAGIC));
            const unsigned by = (unsigned)__float_as_int(__fadd_rz(cyf, FMAGIC));
            const int idx = (int)(by * 64u + bx + KFOLD);   // in [-65, 4095]

            // tap-validity as weight selection (no predicated loads)
            const float mxz = ((ix >= 32.0f) & (ix < 96.0f)) ? mx : 0.0f;
            const float wxz = ((ix >= 31.0f) & (ix < 95.0f)) ? wx : 0.0f;
            const float myz = ((iy >= 32.0f) & (iy < 96.0f)) ? my : 0.0f;
            const float wyz = ((iy >= 31.0f) & (iy < 95.0f)) ? wy : 0.0f;

            const float2 r00 = T2[idx];
            const float2 r10 = T2[idx + 1];
            const float2 r01 = T2[idx + 64];
            const float2 r11 = T2[idx + 65];

            const float w00 = mxz * myz, w10 = wxz * myz;
            const float w01 = mxz * wyz, w11 = wxz * wyz;

            float fv = r00.x * w00, sv = r00.y * w00;
            fv = fmaf(r10.x, w10, fv); sv = fmaf(r10.y, w10, sv);
            fv = fmaf(r01.x, w01, fv); sv = fmaf(r01.y, w01, sv);
            fv = fmaf(r11.x, w11, fv); sv = fmaf(r11.y, w11, sv);

            rfp[k] = fv;
            rsp[k] = sv;
            ix += a00;
            iy += a10;
        }

        __stcs((float4*)&of[o], rf);
        __stcs((float4*)&os[o], rs);
    }
}

extern "C" void kernel_launch(void* const* d_in, const int* in_sizes, int n_in,
                              void* d_out, int out_size) {
    const float* affine = (const float*)d_in[0];   // (N,6) fp32
    const float* fill   = (const float*)d_in[1];   // (N,64,64) fp32
    const float* stroke = (const float*)d_in[2];   // (N,64,64) fp32
    // d_in[3] = targetsize (constant, unused)

    float* out_fill   = (float*)d_out;
    float* out_stroke = (float*)d_out + (size_t)NB * 128 * 128;

    affine_sampler_kernel<<<NB, 512>>>(affine, fill, stroke, out_fill, out_stroke);
}

// round 8
// speedup vs baseline: 2.1701x; 2.1701x over previous
#include <cuda_runtime.h>

#define NB   2048
#define SRC  64
#define PAD  32

#define FMAG  12582912.0f        // 1.5 * 2^23: valid magic floor for v in (-2^22, 2^22)
#define FMAGI 0x4B400000         // bits(FMAG)

__global__ void __launch_bounds__(512, 4)
affine_sampler_kernel(const float* __restrict__ affine,   // (N,6)
                      const float* __restrict__ fill,     // (N,64,64)
                      const float* __restrict__ stroke,   // (N,64,64)
                      float* __restrict__ out_fill,       // (N,128,128)
                      float* __restrict__ out_stroke)     // (N,128,128)
{
    __shared__ float2 T2[SRC * SRC];   // interleaved {fill,stroke}, 32 KB

    const int n   = blockIdx.x;
    const int tid = threadIdx.x;

    // ---- stage + interleave source tiles (float4 global reads, coalesced) ----
    {
        const float4* gf = (const float4*)(fill   + (size_t)n * SRC * SRC);
        const float4* gs = (const float4*)(stroke + (size_t)n * SRC * SRC);
        #pragma unroll
        for (int i = 0; i < 2; i++) {
            const int v = tid + i * 512;          // float4 index 0..1023
            float4 f  = gf[v];
            float4 st = gs[v];
            float2* dst = &T2[v * 4];
            dst[0] = make_float2(f.x, st.x);
            dst[1] = make_float2(f.y, st.y);
            dst[2] = make_float2(f.z, st.z);
            dst[3] = make_float2(f.w, st.w);
        }
    }

    // ---- theta (broadcast loads; every thread computes) ----
    const float* a = affine + n * 6;
    const float a00 = 2.0f / (1.0f + __expf(-a[0]));
    const float a11 = 2.0f / (1.0f + __expf(-a[1]));
    const float a01 = 2.0f * tanhf(a[2]);
    const float a10 = 2.0f * tanhf(a[3]);
    const float a02 = tanhf(a[4]);
    const float a12 = tanhf(a[5]);

    // Folded chain: ix = a00*x + a01*y + Cx  (pixel coords in padded 128x128 img)
    const float Cx = 64.0f * a02 + 63.5f - 63.5f * (a00 + a01);
    const float Cy = 64.0f * a12 + 63.5f - 63.5f * (a10 + a11);

    // row-endpoint deltas over x in [0,127]; a00 > 0 always, a10 sign unknown
    const float ex = 127.0f * a00;
    const float ey = 127.0f * a10;
    // per-k (stride-32) coordinate increments
    const float dxk = 32.0f * a00;
    const float dyk = 32.0f * a10;

    __syncthreads();

    float* of = out_fill   + (size_t)n * 128 * 128;
    float* os = out_stroke + (size_t)n * 128 * 128;

    const int lane = tid & 31;
    const int warp = tid >> 5;              // 0..15; warp owns whole rows
    const float lf = (float)lane;           // strided mapping: x = lane + 32k

    #pragma unroll 1
    for (int it = 0; it < 8; it++) {
        const int   row = it * 16 + warp;
        const float yf  = (float)row;

        // row-start coords (x=0) and row extremes over x in [0,127]
        const float rx0 = fmaf(a01, yf, Cx);
        const float ry0 = fmaf(a11, yf, Cy);
        const float lox = rx0;               // a00 > 0
        const float hix = rx0 + ex;
        const float loy = fminf(ry0, ry0 + ey);
        const float hiy = fmaxf(ry0, ry0 + ey);

        // warp-uniform: entire row exactly zero? (pixel nonzero needs ix,iy in [31,96))
        const bool zero = (hix <= 30.99f) | (lox >= 96.01f) |
                          (hiy <= 30.99f) | (loy >= 96.01f);

        if (zero) {
            // mapping-independent: float4 zero stores
            const int o4 = row * 128 + (lane << 2);
            const float4 z = make_float4(0.f, 0.f, 0.f, 0.f);
            __stcs((float4*)&of[o4], z);
            __stcs((float4*)&os[o4], z);
            continue;
        }

        // ---- work path: predicated taps, conflict-free strided lanes ----
        float ix = fmaf(a00, lf, rx0);
        float iy = fmaf(a10, lf, ry0);
        const int o = row * 128 + lane;

        #pragma unroll
        for (int k = 0; k < 4; k++) {
            // negative-safe magic floor
            const float tx = __fadd_rz(ix, FMAG);
            const float ty = __fadd_rz(iy, FMAG);
            const float x0f = tx - FMAG;
            const float y0f = ty - FMAG;
            const float wx = ix - x0f;
            const float wy = iy - y0f;
            const float mx = 1.0f - wx;
            const float my = 1.0f - wy;

            const int x0 = __float_as_int(tx) - FMAGI;   // floor(ix), in [-66, 97]
            const int y0 = __float_as_int(ty) - FMAGI;

            const bool vx0 = (unsigned)(x0 - PAD)     < 64u;
            const bool vx1 = (unsigned)(x0 - PAD + 1) < 64u;
            const bool vy0 = (unsigned)(y0 - PAD)     < 64u;
            const bool vy1 = (unsigned)(y0 - PAD + 1) < 64u;

            const int base = (y0 - PAD) * SRC + (x0 - PAD);

            float fv = 0.0f, sv = 0.0f;
            if (vx0 & vy0) { float2 r = T2[base];      float w = mx * my; fv = fmaf(r.x, w, fv); sv = fmaf(r.y, w, sv); }
            if (vx1 & vy0) { float2 r = T2[base + 1];  float w = wx * my; fv = fmaf(r.x, w, fv); sv = fmaf(r.y, w, sv); }
            if (vx0 & vy1) { float2 r = T2[base + 64]; float w = mx * wy; fv = fmaf(r.x, w, fv); sv = fmaf(r.y, w, sv); }
            if (vx1 & vy1) { float2 r = T2[base + 65]; float w = wx * wy; fv = fmaf(r.x, w, fv); sv = fmaf(r.y, w, sv); }

            __stcs(&of[o + 32 * k], fv);
            __stcs(&os[o + 32 * k], sv);

            ix += dxk;
            iy += dyk;
        }
    }
}

extern "C" void kernel_launch(void* const* d_in, const int* in_sizes, int n_in,
                              void* d_out, int out_size) {
    const float* affine = (const float*)d_in[0];   // (N,6) fp32
    const float* fill   = (const float*)d_in[1];   // (N,64,64) fp32
    const float* stroke = (const float*)d_in[2];   // (N,64,64) fp32
    // d_in[3] = targetsize (constant, unused)

    float* out_fill   = (float*)d_out;
    float* out_stroke = (float*)d_out + (size_t)NB * 128 * 128;

    affine_sampler_kernel<<<NB, 512>>>(affine, fill, stroke, out_fill, out_stroke);
}

// round 9
// speedup vs baseline: 2.3369x; 1.0768x over previous
#include <cuda_runtime.h>

#define NB   2048
#define SRC  64
#define PAD  32

#define FMAG  12582912.0f        // 1.5 * 2^23: magic floor, valid for |v| < 2^22
#define FMAGI 0x4B400000         // bits(FMAG)
// idx = bits(ty)*64 + bits(tx) + KFOLD == (y0-32)*64 + (x0-32)
#define KFOLD (0u - (0x4B400000u * 65u + 2080u))

__global__ void __launch_bounds__(512, 3)
affine_sampler_kernel(const float* __restrict__ affine,   // (N,6)
                      const float* __restrict__ fill,     // (N,64,64)
                      const float* __restrict__ stroke,   // (N,64,64)
                      float* __restrict__ out_fill,       // (N,128,128)
                      float* __restrict__ out_stroke)     // (N,128,128)
{
    __shared__ float2 T2[SRC * SRC];   // interleaved {fill,stroke}, 32 KB

    const int n   = blockIdx.x;
    const int tid = threadIdx.x;

    // ---- stage + interleave source tiles (float4 global reads, coalesced) ----
    {
        const float4* gf = (const float4*)(fill   + (size_t)n * SRC * SRC);
        const float4* gs = (const float4*)(stroke + (size_t)n * SRC * SRC);
        #pragma unroll
        for (int i = 0; i < 2; i++) {
            const int v = tid + i * 512;          // float4 index 0..1023
            float4 f  = gf[v];
            float4 st = gs[v];
            float2* dst = &T2[v * 4];
            dst[0] = make_float2(f.x, st.x);
            dst[1] = make_float2(f.y, st.y);
            dst[2] = make_float2(f.z, st.z);
            dst[3] = make_float2(f.w, st.w);
        }
    }

    // ---- theta (broadcast loads; every thread computes) ----
    const float* a = affine + n * 6;
    const float a00 = 2.0f / (1.0f + __expf(-a[0]));
    const float a11 = 2.0f / (1.0f + __expf(-a[1]));
    const float a01 = 2.0f * tanhf(a[2]);
    const float a10 = 2.0f * tanhf(a[3]);
    const float a02 = tanhf(a[4]);
    const float a12 = tanhf(a[5]);

    // Folded chain: ix = a00*x + a01*y + Cx  (pixel coords in padded 128x128 img)
    const float Cx = 64.0f * a02 + 63.5f - 63.5f * (a00 + a01);
    const float Cy = 64.0f * a12 + 63.5f - 63.5f * (a10 + a11);

    const float inv00 = 1.0f / a00;     // a00 > 0 always
    const float inv10 = 1.0f / a10;     // may be +/-inf; handled conservatively

    __syncthreads();

    float* of = out_fill   + (size_t)n * 128 * 128;
    float* os = out_stroke + (size_t)n * 128 * 128;

    const int lane = tid & 31;
    const int warp = tid >> 5;              // 0..15; warp owns whole rows
    const float lf = (float)lane;           // strided mapping: x = lane + 32k

    #pragma unroll 1
    for (int it = 0; it < 8; it++) {
        const int   row = it * 16 + warp;
        const float yf  = (float)row;

        // row-start coords (x = 0)
        const float rx0 = fmaf(a01, yf, Cx);
        const float ry0 = fmaf(a11, yf, Cy);

        // ---- interval algebra over x (all warp-uniform) ----
        // certainly-zero region: x <= zL  or  x >= zH
        const float zxl = (30.99f - rx0) * inv00;
        const float zxh = (96.01f - rx0) * inv00;
        const float tz1 = (30.99f - ry0) * inv10;
        const float tz2 = (96.01f - ry0) * inv10;
        const float zL  = fmaxf(zxl, fminf(tz1, tz2));
        const float zH  = fminf(zxh, fmaxf(tz1, tz2));
        // all-taps-valid region: IL <= x <= IH
        const float ixl = (32.01f - rx0) * inv00;
        const float ixh = (94.99f - rx0) * inv00;
        const float tu1 = (32.01f - ry0) * inv10;
        const float tu2 = (94.99f - ry0) * inv10;
        const float IL  = fmaxf(ixl, fminf(tu1, tu2));
        const float IH  = fminf(ixh, fmaxf(tu1, tu2));

        // whole row certainly zero?
        if ((127.0f <= zL) | (0.0f >= zH) | (zH <= zL)) {
            const int o4 = row * 128 + (lane << 2);
            const float4 z = make_float4(0.f, 0.f, 0.f, 0.f);
            __stcs((float4*)&of[o4], z);
            __stcs((float4*)&os[o4], z);
            continue;
        }

        const int o = row * 128 + lane;

        #pragma unroll
        for (int k = 0; k < 4; k++) {
            const float c0 = (float)(32 * k);
            const float c1 = (float)(32 * k + 31);

            if ((c1 <= zL) | (c0 >= zH)) {
                // ---- chunk certainly zero ----
                __stcs(&of[o + 32 * k], 0.0f);
                __stcs(&os[o + 32 * k], 0.0f);
            } else {
                const float xk = lf + c0;
                float ix = fmaf(a00, xk, rx0);
                float iy = fmaf(a10, xk, ry0);

                const float tx = __fadd_rz(ix, FMAG);
                const float ty = __fadd_rz(iy, FMAG);
                const float wx = ix - (tx - FMAG);
                const float wy = iy - (ty - FMAG);

                if ((c0 >= IL) & (c1 <= IH)) {
                    // ---- interior chunk: unconditional taps, lerp form ----
                    const unsigned idx = (unsigned)__float_as_int(ty) * 64u
                                       + (unsigned)__float_as_int(tx) + KFOLD;
                    const float2 r00 = T2[idx];
                    const float2 r10 = T2[idx + 1];
                    const float2 r01 = T2[idx + 64];
                    const float2 r11 = T2[idx + 65];

                    const float ftop = fmaf(wx, r10.x - r00.x, r00.x);
                    const float fbot = fmaf(wx, r11.x - r01.x, r01.x);
                    const float stop = fmaf(wx, r10.y - r00.y, r00.y);
                    const float sbot = fmaf(wx, r11.y - r01.y, r01.y);

                    __stcs(&of[o + 32 * k], fmaf(wy, fbot - ftop, ftop));
                    __stcs(&os[o + 32 * k], fmaf(wy, sbot - stop, stop));
                } else {
                    // ---- generic boundary chunk: predicated taps ----
                    const float mx = 1.0f - wx;
                    const float my = 1.0f - wy;
                    const int x0 = __float_as_int(tx) - FMAGI;
                    const int y0 = __float_as_int(ty) - FMAGI;

                    const bool vx0 = (unsigned)(x0 - PAD)     < 64u;
                    const bool vx1 = (unsigned)(x0 - PAD + 1) < 64u;
                    const bool vy0 = (unsigned)(y0 - PAD)     < 64u;
                    const bool vy1 = (unsigned)(y0 - PAD + 1) < 64u;

                    const int base = (y0 - PAD) * SRC + (x0 - PAD);

                    float fv = 0.0f, sv = 0.0f;
                    if (vx0 & vy0) { float2 r = T2[base];      float w = mx * my; fv = fmaf(r.x, w, fv); sv = fmaf(r.y, w, sv); }
                    if (vx1 & vy0) { float2 r = T2[base + 1];  float w = wx * my; fv = fmaf(r.x, w, fv); sv = fmaf(r.y, w, sv); }
                    if (vx0 & vy1) { float2 r = T2[base + 64]; float w = mx * wy; fv = fmaf(r.x, w, fv); sv = fmaf(r.y, w, sv); }
                    if (vx1 & vy1) { float2 r = T2[base + 65]; float w = wx * wy; fv = fmaf(r.x, w, fv); sv = fmaf(r.y, w, sv); }

                    __stcs(&of[o + 32 * k], fv);
                    __stcs(&os[o + 32 * k], sv);
                }
            }
        }
    }
}

extern "C" void kernel_launch(void* const* d_in, const int* in_sizes, int n_in,
                              void* d_out, int out_size) {
    const float* affine = (const float*)d_in[0];   // (N,6) fp32
    const float* fill   = (const float*)d_in[1];   // (N,64,64) fp32
    const float* stroke = (const float*)d_in[2];   // (N,64,64) fp32
    // d_in[3] = targetsize (constant, unused)

    float* out_fill   = (float*)d_out;
    float* out_stroke = (float*)d_out + (size_t)NB * 128 * 128;

    affine_sampler_kernel<<<NB, 512>>>(affine, fill, stroke, out_fill, out_stroke);
}